// round 13
// baseline (speedup 1.0000x reference)
#include <cuda_runtime.h>
#include <cstdint>
#include <cstddef>

// ---------------------------------------------------------------------------
// VideoEncoder: 3x Conv3D (stride 1,2,2; pad 1) + VQ argmin + embedding gather
// R13: convs = scalar FFMA GEMM with ONE sync per k-chunk (2-stage smem);
//      vq_p1 = 32-k chunks (half the syncs) + pointer-based addressing.
// ---------------------------------------------------------------------------

__device__ float g_h1[2 * 128 * 16 * 64 * 64];   // 64 MB
__device__ float g_h2[2 * 256 * 16 * 32 * 32];   // 32 MB
__device__ float g_f [2 * 512 * 16 * 16 * 16];   // 16 MB
__device__ float g_Af[512 * 64 * 32 * 4];        // 16 MB  f  tf32 A-fragments
__device__ float g_Bf[1024 * 64 * 32 * 2];       // 16 MB  cb tf32 B-fragments
__device__ float g_c2[8192];
__device__ float g_ps[16 * 8192];
__device__ int   g_pi[16 * 8192];

// ---------------------------------------------------------------------------
// helpers
// ---------------------------------------------------------------------------
__device__ __forceinline__ uint32_t smem_u32(const void* p) {
    uint32_t a;
    asm("{ .reg .u64 t; cvta.to.shared.u64 t, %1; cvt.u32.u64 %0, t; }"
        : "=r"(a) : "l"(p));
    return a;
}
__device__ __forceinline__ void cp16(uint32_t s, const void* g) {
    asm volatile("cp.async.cg.shared.global [%0], [%1], 16;" :: "r"(s), "l"(g));
}
__device__ __forceinline__ void cpcommit() {
    asm volatile("cp.async.commit_group;" ::: "memory");
}
template<int N> __device__ __forceinline__ void cpwait() {
    asm volatile("cp.async.wait_group %0;" :: "n"(N) : "memory");
}
__device__ __forceinline__ float tf32of(float x) {
    uint32_t b;
    asm("cvt.rna.tf32.f32 %0, %1;" : "=r"(b) : "f"(x));
    return __uint_as_float(b);
}
__device__ __forceinline__ void mma8(float* c, const uint32_t* a, const uint32_t* b) {
    asm volatile("mma.sync.aligned.m16n8k8.row.col.f32.tf32.tf32.f32 "
        "{%0,%1,%2,%3}, {%4,%5,%6,%7}, {%8,%9}, {%0,%1,%2,%3};"
        : "+f"(c[0]), "+f"(c[1]), "+f"(c[2]), "+f"(c[3])
        : "r"(a[0]), "r"(a[1]), "r"(a[2]), "r"(a[3]), "r"(b[0]), "r"(b[1]));
}

// ---------------------------------------------------------------------------
// conv3d scalar GEMM body — R6 microkernel, restructured to ONE sync per
// k-chunk via 2-stage smem double buffering. FMA order per accumulator is
// unchanged (bitwise-identical outputs).
// FSPLIT: scatter tf32 A-fragments of the output (conv3 -> VQ operand).
// ---------------------------------------------------------------------------
template<int CIN, int CO, int OT, int IH, int IW, int OH, int OW, bool RELU, bool FSPLIT>
__device__ __forceinline__ void conv3d_body(
    const float* __restrict__ x, const float* __restrict__ w,
    const float* __restrict__ bias, float* __restrict__ y,
    float* __restrict__ af, int bx, int by)
{
    constexpr int K   = CIN * 27;
    constexpr int IT  = OT;
    constexpr int SPO = OT * OH * OW;
    constexpr int NCH = (K + 15) / 16;

    __shared__ float Ws[2][16][128];
    __shared__ float Xs[2][16][128];

    const int tid = threadIdx.x;
    const int pt  = bx * 128;
    const int cot = by * 128;
    const int b   = pt / SPO;
    const int sp0 = pt - b * SPO;

    const int xk = tid >> 4;
    const int xp = (tid & 15) * 8;
    const int spx = sp0 + xp;
    const int t0  = spx / (OH * OW);
    const int rhw = spx % (OH * OW);
    const int h0  = rhw / OW;
    const int w0  = rhw % OW;
    const float* xb = x + (size_t)b * CIN * (IT * IH * IW);

    const int wc = tid >> 1;
    const int wk = (tid & 1) * 8;
    const float* wrow = w + (size_t)(cot + wc) * K;

    const int tr = tid >> 4;
    const int tc = tid & 15;

    float wbuf[8], xbuf[8];
    float acc[8][8];
#pragma unroll
    for (int i = 0; i < 8; i++)
#pragma unroll
        for (int j = 0; j < 8; j++) acc[i][j] = 0.f;

    auto loadW = [&](int k0) {
        if constexpr (K % 16 == 0) {
            float4 v0 = *(const float4*)(wrow + k0 + wk);
            float4 v1 = *(const float4*)(wrow + k0 + wk + 4);
            wbuf[0] = v0.x; wbuf[1] = v0.y; wbuf[2] = v0.z; wbuf[3] = v0.w;
            wbuf[4] = v1.x; wbuf[5] = v1.y; wbuf[6] = v1.z; wbuf[7] = v1.w;
        } else {
#pragma unroll
            for (int q = 0; q < 8; q++) {
                int k = k0 + wk + q;
                wbuf[q] = (k < K) ? wrow[k] : 0.f;
            }
        }
    };
    auto loadX = [&](int k0) {
        int k = k0 + xk;
        if constexpr (K % 16 != 0) {
            if (k >= K) {
#pragma unroll
                for (int q = 0; q < 8; q++) xbuf[q] = 0.f;
                return;
            }
        }
        int ci = k / 27, tap = k - ci * 27;
        int kt = tap / 9, r9 = tap - kt * 9;
        int kh = r9 / 3,  kw = r9 - kh * 3;
        int it  = t0 + kt - 1;
        int ih  = 2 * h0 + kh - 1;
        int iw0 = 2 * w0 + kw - 1;
        bool okp = ((unsigned)it < (unsigned)IT) && ((unsigned)ih < (unsigned)IH);
        const float* px = xb + ((size_t)ci * IT + it) * (IH * IW) + (long)ih * IW;
#pragma unroll
        for (int q = 0; q < 8; q++) {
            int iw = iw0 + 2 * q;
            bool ok = okp && ((unsigned)iw < (unsigned)IW);
            xbuf[q] = ok ? px[iw] : 0.f;
        }
    };

    loadW(0);
    loadX(0);

    for (int c0 = 0; c0 < NCH; c0++) {
        const int s = c0 & 1;
        // store chunk c0 (regs -> stage s); safe: last readers of stage s
        // (compute c0-2) all passed the sync at iter c0-1.
#pragma unroll
        for (int q = 0; q < 8; q++) Ws[s][wk + q][wc] = wbuf[q];
        *(float4*)&Xs[s][xk][xp]     = *(float4*)&xbuf[0];
        *(float4*)&Xs[s][xk][xp + 4] = *(float4*)&xbuf[4];
        __syncthreads();
        if (c0 + 1 < NCH) { loadW((c0 + 1) * 16); loadX((c0 + 1) * 16); }

#pragma unroll
        for (int kk = 0; kk < 16; kk++) {
            float a[8], bxr[8];
            *(float4*)&a[0]   = *(const float4*)&Ws[s][kk][tr * 8];
            *(float4*)&a[4]   = *(const float4*)&Ws[s][kk][tr * 8 + 4];
            *(float4*)&bxr[0] = *(const float4*)&Xs[s][kk][tc * 8];
            *(float4*)&bxr[4] = *(const float4*)&Xs[s][kk][tc * 8 + 4];
#pragma unroll
            for (int i = 0; i < 8; i++)
#pragma unroll
                for (int j = 0; j < 8; j++)
                    acc[i][j] = fmaf(a[i], bxr[j], acc[i][j]);
        }
    }

#pragma unroll
    for (int i = 0; i < 8; i++) {
        int co = cot + tr * 8 + i;
        float bv = bias[co];
        float o[8];
#pragma unroll
        for (int j = 0; j < 8; j++) {
            float v = acc[i][j] + bv;
            if (RELU) v = fmaxf(v, 0.f);
            o[j] = v;
        }
        float* yp = y + (size_t)(b * CO + co) * SPO + sp0 + tc * 8;
        *(float4*)yp       = *(float4*)&o[0];
        *(float4*)(yp + 4) = *(float4*)&o[4];
        if constexpr (FSPLIT) {
            int kt = co >> 3, kc = co & 7;
            int lc = kc & 3, khalf = kc >> 2;
#pragma unroll
            for (int j = 0; j < 8; j++) {
                int pos = pt + tc * 8 + j;
                int r   = pos & 15;
                int lane = (r & 7) * 4 + lc;
                int q    = khalf * 2 + (r >> 3);
                af[((size_t)((pos >> 4) * 64 + kt) * 32 + lane) * 4 + q] = tf32of(o[j]);
            }
        }
    }
}

// conv2 (plain)
template<int CIN, int CO, int OT, int IH, int IW, int OH, int OW, bool RELU>
__global__ void __launch_bounds__(256, 2) conv3d_kernel(
    const float* __restrict__ x, const float* __restrict__ w,
    const float* __restrict__ bias, float* __restrict__ y)
{
    conv3d_body<CIN, CO, OT, IH, IW, OH, OW, RELU, false>(
        x, w, bias, y, nullptr, blockIdx.x, blockIdx.y);
}

// conv1 grid-fused with codebook fragment split + c2
__global__ void __launch_bounds__(256, 2) conv1_cb_kernel(
    const float* __restrict__ x, const float* __restrict__ w,
    const float* __restrict__ bias, float* __restrict__ y,
    const float* __restrict__ cb, float* __restrict__ bf, float* __restrict__ c2)
{
    if (blockIdx.x < 1024) {
        conv3d_body<3, 128, 16, 128, 128, 64, 64, true, false>(
            x, w, bias, y, nullptr, blockIdx.x, 0);
        return;
    }
    const int blk  = blockIdx.x - 1024;          // 0..255
    const int wid  = threadIdx.x >> 5;
    const int lane = threadIdx.x & 31;
    const int lr = lane >> 2, lc = lane & 3;
    const int nt = blk * 4 + (wid & 3);
    const float* row = cb + (size_t)(nt * 8 + lr) * 512;
    for (int i = 0; i < 32; i++) {
        int kt = (wid >> 2) + 2 * i;
        float b0 = tf32of(row[kt * 8 + lc]);
        float b1 = tf32of(row[kt * 8 + lc + 4]);
        *(float2*)(bf + ((size_t)(nt * 64 + kt) * 32 + lane) * 2) = make_float2(b0, b1);
    }
#pragma unroll
    for (int rr = 0; rr < 4; rr++) {
        int v = blk * 32 + wid * 4 + rr;
        const float* r = cb + (size_t)v * 512;
        float s = 0.f;
#pragma unroll 4
        for (int c = lane; c < 512; c += 32) { float xv = r[c]; s = fmaf(xv, xv, s); }
#pragma unroll
        for (int off = 16; off; off >>= 1) s += __shfl_down_sync(0xffffffffu, s, off);
        if (lane == 0) c2[v] = s;
    }
}

// conv3 with A-fragment scatter fused in epilogue
__global__ void __launch_bounds__(256, 2) conv3_fs_kernel(
    const float* __restrict__ x, const float* __restrict__ w,
    const float* __restrict__ bias, float* __restrict__ y, float* __restrict__ af)
{
    conv3d_body<256, 512, 16, 32, 32, 16, 16, false, true>(
        x, w, bias, y, af, blockIdx.x, blockIdx.y);
}

// ---------------------------------------------------------------------------
// Pass 1: single-MMA tf32 approx distances, best-2 per (pos, segment).
// grid (64 pos-tiles, 8 segments), 256 threads, 2 CTAs/SM.
// 32-k chunks (16 per tile), 3-stage cp.async pipeline, 1 sync per chunk.
// Stage (8192 floats): A [mtl(8)][ktl(4)][128], B at +4096 [ntl(16)][ktl(4)][64]
// ---------------------------------------------------------------------------
static constexpr int P1_SMEM = 3 * 8192 * 4;   // 96 KB

__global__ void __launch_bounds__(256, 2) vq_p1_kernel(
    const float* __restrict__ Af, const float* __restrict__ Bf,
    const float* __restrict__ c2,
    float* __restrict__ partS, int* __restrict__ partI)
{
    extern __shared__ float sm[];

    const int tid  = threadIdx.x;
    const int lane = tid & 31;
    const int wid  = tid >> 5;
    const int lr   = lane >> 2, lc = lane & 3;
    const int mw   = wid >> 2,  nw = wid & 3;

    const int pt  = blockIdx.x * 128;
    const int seg = blockIdx.y;
    const int mt0 = blockIdx.x * 8;

    // per-thread loader slots (4 A + 4 B), pointer-based addressing
    const float* aBase[4];
    uint32_t     aDst[4];
    size_t       bOffSrc[4];
    uint32_t     bDst[4];
#pragma unroll
    for (int i = 0; i < 4; i++) {
        int slot = tid + i * 256;                 // 0..1023
        int ln  = slot & 31;
        int ktA = (slot >> 5) & 3;
        int mtl = slot >> 7;                      // 0..7
        aBase[i] = Af + ((size_t)((mt0 + mtl) * 64 + ktA) * 32 + ln) * 4;
        aDst[i]  = (uint32_t)((mtl * 4 + ktA) * 128 + ln * 4);
        int lp  = slot & 15;
        int ktB = (slot >> 4) & 3;
        int ntl = slot >> 6;                      // 0..15
        bOffSrc[i] = ((size_t)(ntl * 64 + ktB) * 32 + lp * 2) * 2;
        bDst[i]    = (uint32_t)(4096 + (ntl * 4 + ktB) * 64 + lp * 4);
    }

    float s1[8], s2[8];
    int   i1[8], i2[8];
#pragma unroll
    for (int i = 0; i < 8; i++) { s1[i] = 3.4e38f; s2[i] = 3.4e38f; i1[i] = 0; i2[i] = 0; }

    for (int tile = 0; tile < 8; tile++) {
        const int nt0 = seg * 128 + tile * 16;
        const int vt  = seg * 1024 + tile * 128;
        const float* bTile = Bf + (size_t)nt0 * 4096;

        float acc[4][4][4];
#pragma unroll
        for (int a = 0; a < 4; a++)
#pragma unroll
            for (int c = 0; c < 4; c++)
#pragma unroll
                for (int r = 0; r < 4; r++) acc[a][c][r] = 0.f;

        auto issue = [&](int ch, int s) {
            uint32_t st = smem_u32(sm + s * 8192);
#pragma unroll
            for (int i = 0; i < 4; i++)
                cp16(st + aDst[i] * 4, aBase[i] + ch * 512);
#pragma unroll
            for (int i = 0; i < 4; i++)
                cp16(st + bDst[i] * 4, bTile + bOffSrc[i] + ch * 256);
            cpcommit();
        };

        issue(0, 0);
        issue(1, 1);
        for (int ch = 0; ch < 16; ch++) {
            if (ch < 15) cpwait<1>(); else cpwait<0>();
            __syncthreads();
            if (ch + 2 < 16) issue(ch + 2, (ch + 2) % 3);

            const float* st = sm + (ch % 3) * 8192;
#pragma unroll
            for (int ktl = 0; ktl < 4; ktl++) {
                uint32_t ah[4][4], bh[4][2];
#pragma unroll
                for (int mf = 0; mf < 4; mf++)
                    *(float4*)&ah[mf][0] = *(const float4*)(
                        st + ((mw * 4 + mf) * 4 + ktl) * 128 + lane * 4);
#pragma unroll
                for (int nf = 0; nf < 4; nf++)
                    *(float2*)&bh[nf][0] = *(const float2*)(
                        st + 4096 + ((nw * 4 + nf) * 4 + ktl) * 64 + lane * 2);
#pragma unroll
                for (int mf = 0; mf < 4; mf++)
#pragma unroll
                    for (int nf = 0; nf < 4; nf++)
                        mma8(acc[mf][nf], ah[mf], bh[nf]);
            }
        }
        __syncthreads();   // stage reuse across tiles

#pragma unroll
        for (int mf = 0; mf < 4; mf++)
#pragma unroll
            for (int half = 0; half < 2; half++) {
                int bs = mf * 2 + half;
#pragma unroll
                for (int nf = 0; nf < 4; nf++)
#pragma unroll
                    for (int r = 0; r < 2; r++) {
                        int col = vt + (nw * 4 + nf) * 8 + 2 * lc + r;
                        float d = fmaf(-2.f, acc[mf][nf][half * 2 + r],
                                       __ldg(&c2[col]));
                        if (d < s1[bs]) {
                            s2[bs] = s1[bs]; i2[bs] = i1[bs];
                            s1[bs] = d;      i1[bs] = col;
                        } else if (d < s2[bs]) {
                            s2[bs] = d;      i2[bs] = col;
                        }
                    }
            }
    }

    // reduction: 16 contributors x best-2 per row
    __syncthreads();
    float* redS = sm;                 // [128][32]
    int*   redI = (int*)(sm + 4096);  // [128][32]
#pragma unroll
    for (int mf = 0; mf < 4; mf++)
#pragma unroll
        for (int half = 0; half < 2; half++) {
            int bs   = mf * 2 + half;
            int row  = mw * 64 + mf * 16 + half * 8 + lr;
            int cont = nw * 4 + lc;
            redS[row * 32 + cont * 2]     = s1[bs];
            redS[row * 32 + cont * 2 + 1] = s2[bs];
            redI[row * 32 + cont * 2]     = i1[bs];
            redI[row * 32 + cont * 2 + 1] = i2[bs];
        }
    __syncthreads();
    if (tid < 128) {
        float b1 = 3.4e38f, b2 = 3.4e38f;
        int   j1 = 0, j2 = 0;
#pragma unroll
        for (int q = 0; q < 32; q++) {
            float v = redS[tid * 32 + q];
            int   i = redI[tid * 32 + q];
            if (v < b1) { b2 = b1; j2 = j1; b1 = v; j1 = i; }
            else if (v < b2) { b2 = v; j2 = i; }
        }
        int pos = pt + tid;
        partS[(seg * 2 + 0) * 8192 + pos] = b1;
        partI[(seg * 2 + 0) * 8192 + pos] = j1;
        partS[(seg * 2 + 1) * 8192 + pos] = b2;
        partI[(seg * 2 + 1) * 8192 + pos] = j2;
    }
}

// ---------------------------------------------------------------------------
// Pass 2: exact fp32 re-score of 16 candidates per position; the winning
// warp then copies the embedding row (gather fused). One warp/pos.
// ---------------------------------------------------------------------------
__global__ void __launch_bounds__(256) vq_p2_kernel(
    const float* __restrict__ f, const float* __restrict__ cb,
    const int* __restrict__ partI, const float* __restrict__ emb,
    float* __restrict__ outTok, float* __restrict__ outEmb, int writeTok)
{
    const int wid  = threadIdx.x >> 5;
    const int lane = threadIdx.x & 31;
    const int pos  = blockIdx.x * 8 + wid;
    const int b    = pos >> 12;
    const int sp   = pos & 4095;

    float fv[16];
#pragma unroll
    for (int t = 0; t < 16; t++)
        fv[t] = f[((size_t)b * 512 + lane + 32 * t) * 4096 + sp];

    float best = 3.4e38f;
    int   bi   = 0x7fffffff;
#pragma unroll 1
    for (int j = 0; j < 16; j++) {
        int v = partI[j * 8192 + pos];
        const float* cr = cb + (size_t)v * 512;
        float dot = 0.f, cc = 0.f;
#pragma unroll
        for (int t = 0; t < 16; t++) {
            float cv = cr[lane + 32 * t];
            dot = fmaf(fv[t], cv, dot);
            cc  = fmaf(cv, cv, cc);
        }
#pragma unroll
        for (int off = 16; off; off >>= 1) {
            dot += __shfl_down_sync(0xffffffffu, dot, off);
            cc  += __shfl_down_sync(0xffffffffu, cc,  off);
        }
        if (lane == 0) {
            float d = fmaf(-2.f, dot, cc);
            if (d < best || (d == best && v < bi)) { best = d; bi = v; }
        }
    }
    bi = __shfl_sync(0xffffffffu, bi, 0);
    if (lane == 0 && writeTok) outTok[pos] = (float)bi;
    const float4* src = (const float4*)(emb + (size_t)bi * 512);
    float4*       dst = (float4*)(outEmb + (size_t)pos * 512);
#pragma unroll
    for (int t = 0; t < 4; t++)
        dst[lane + 32 * t] = src[lane + 32 * t];
}

// ---------------------------------------------------------------------------
// launch (vq_p1 is the 4th launch -> profiled by ncu)
// ---------------------------------------------------------------------------
extern "C" void kernel_launch(void* const* d_in, const int* in_sizes, int n_in,
                              void* d_out, int out_size)
{
    const float* video = (const float*)d_in[0];
    const float* w1    = (const float*)d_in[1];
    const float* b1    = (const float*)d_in[2];
    const float* w2    = (const float*)d_in[3];
    const float* b2    = (const float*)d_in[4];
    const float* w3    = (const float*)d_in[5];
    const float* b3    = (const float*)d_in[6];
    const float* cb    = (const float*)d_in[7];
    const float* emb   = (const float*)d_in[8];

    float *h1, *h2, *ff, *af, *bf, *c2, *ps;
    int *pi;
    cudaGetSymbolAddress((void**)&h1, g_h1);
    cudaGetSymbolAddress((void**)&h2, g_h2);
    cudaGetSymbolAddress((void**)&ff, g_f);
    cudaGetSymbolAddress((void**)&af, g_Af);
    cudaGetSymbolAddress((void**)&bf, g_Bf);
    cudaGetSymbolAddress((void**)&c2, g_c2);
    cudaGetSymbolAddress((void**)&ps, g_ps);
    cudaGetSymbolAddress((void**)&pi, g_pi);

    cudaFuncSetAttribute(vq_p1_kernel,
                         cudaFuncAttributeMaxDynamicSharedMemorySize, P1_SMEM);

    // 1: conv1 + codebook fragment split + c2
    conv1_cb_kernel<<<1024 + 256, 256>>>(video, w1, b1, h1, cb, bf, c2);
    // 2: conv2
    conv3d_kernel<128, 256, 16, 64, 64, 32, 32, true>
        <<<dim3(256, 2), 256>>>(h1, w2, b2, h2);
    // 3: conv3 + f fragment scatter
    conv3_fs_kernel<<<dim3(64, 4), 256>>>(h2, w3, b3, ff, af);
    // 4: VQ pass 1 (profiled)
    vq_p1_kernel<<<dim3(64, 8), 256, P1_SMEM>>>(af, bf, c2, ps, pi);

    float* outf = (float*)d_out;
    const int embElems = 8192 * 512;
    int writeTok = (out_size >= embElems + 8192) ? 1 : 0;
    float* embOut = outf + (writeTok ? 8192 : 0);

    // 5: VQ pass 2 (exact re-score + fused embedding gather)
    vq_p2_kernel<<<1024, 256>>>(ff, cb, pi, emb, outf, embOut, writeTok);
}

// round 14
// speedup vs baseline: 1.0464x; 1.0464x over previous
#include <cuda_runtime.h>
#include <cstdint>
#include <cstddef>

// ---------------------------------------------------------------------------
// VideoEncoder: 3x Conv3D (stride 1,2,2; pad 1) + VQ argmin + embedding gather
// R14: recombination of measured-best components:
//   - convs: R11 scalar FFMA GEMM, single smem stage, two syncs/chunk
//   - vq_p1: R13 32-k-chunk 3-stage pipeline (431us, tensor 52.9%)
//   - vq_p2: exact re-score with fused embedding gather
// ---------------------------------------------------------------------------

__device__ float g_h1[2 * 128 * 16 * 64 * 64];   // 64 MB
__device__ float g_h2[2 * 256 * 16 * 32 * 32];   // 32 MB
__device__ float g_f [2 * 512 * 16 * 16 * 16];   // 16 MB
__device__ float g_Af[512 * 64 * 32 * 4];        // 16 MB  f  tf32 A-fragments
__device__ float g_Bf[1024 * 64 * 32 * 2];       // 16 MB  cb tf32 B-fragments
__device__ float g_c2[8192];
__device__ float g_ps[16 * 8192];
__device__ int   g_pi[16 * 8192];

// ---------------------------------------------------------------------------
// helpers
// ---------------------------------------------------------------------------
__device__ __forceinline__ uint32_t smem_u32(const void* p) {
    uint32_t a;
    asm("{ .reg .u64 t; cvta.to.shared.u64 t, %1; cvt.u32.u64 %0, t; }"
        : "=r"(a) : "l"(p));
    return a;
}
__device__ __forceinline__ void cp16(uint32_t s, const void* g) {
    asm volatile("cp.async.cg.shared.global [%0], [%1], 16;" :: "r"(s), "l"(g));
}
__device__ __forceinline__ void cpcommit() {
    asm volatile("cp.async.commit_group;" ::: "memory");
}
template<int N> __device__ __forceinline__ void cpwait() {
    asm volatile("cp.async.wait_group %0;" :: "n"(N) : "memory");
}
__device__ __forceinline__ float tf32of(float x) {
    uint32_t b;
    asm("cvt.rna.tf32.f32 %0, %1;" : "=r"(b) : "f"(x));
    return __uint_as_float(b);
}
__device__ __forceinline__ void mma8(float* c, const uint32_t* a, const uint32_t* b) {
    asm volatile("mma.sync.aligned.m16n8k8.row.col.f32.tf32.tf32.f32 "
        "{%0,%1,%2,%3}, {%4,%5,%6,%7}, {%8,%9}, {%0,%1,%2,%3};"
        : "+f"(c[0]), "+f"(c[1]), "+f"(c[2]), "+f"(c[3])
        : "r"(a[0]), "r"(a[1]), "r"(a[2]), "r"(a[3]), "r"(b[0]), "r"(b[1]));
}

// ---------------------------------------------------------------------------
// conv3d scalar GEMM body (R2/R6/R11 microkernel — the proven one).
// FSPLIT: scatter tf32 A-fragments of the output (conv3 -> VQ operand).
// ---------------------------------------------------------------------------
template<int CIN, int CO, int OT, int IH, int IW, int OH, int OW, bool RELU, bool FSPLIT>
__device__ __forceinline__ void conv3d_body(
    const float* __restrict__ x, const float* __restrict__ w,
    const float* __restrict__ bias, float* __restrict__ y,
    float* __restrict__ af, int bx, int by)
{
    constexpr int K   = CIN * 27;
    constexpr int IT  = OT;
    constexpr int SPO = OT * OH * OW;
    constexpr int NCH = (K + 15) / 16;

    __shared__ float Ws[16][128];
    __shared__ float Xs[16][128];

    const int tid = threadIdx.x;
    const int pt  = bx * 128;
    const int cot = by * 128;
    const int b   = pt / SPO;
    const int sp0 = pt - b * SPO;

    const int xk = tid >> 4;
    const int xp = (tid & 15) * 8;
    const int spx = sp0 + xp;
    const int t0  = spx / (OH * OW);
    const int rhw = spx % (OH * OW);
    const int h0  = rhw / OW;
    const int w0  = rhw % OW;
    const float* xb = x + (size_t)b * CIN * (IT * IH * IW);

    const int wc = tid >> 1;
    const int wk = (tid & 1) * 8;
    const float* wrow = w + (size_t)(cot + wc) * K;

    const int tr = tid >> 4;
    const int tc = tid & 15;

    float wbuf[8], xbuf[8];
    float acc[8][8];
#pragma unroll
    for (int i = 0; i < 8; i++)
#pragma unroll
        for (int j = 0; j < 8; j++) acc[i][j] = 0.f;

    auto loadW = [&](int k0) {
        if constexpr (K % 16 == 0) {
            float4 v0 = *(const float4*)(wrow + k0 + wk);
            float4 v1 = *(const float4*)(wrow + k0 + wk + 4);
            wbuf[0] = v0.x; wbuf[1] = v0.y; wbuf[2] = v0.z; wbuf[3] = v0.w;
            wbuf[4] = v1.x; wbuf[5] = v1.y; wbuf[6] = v1.z; wbuf[7] = v1.w;
        } else {
#pragma unroll
            for (int q = 0; q < 8; q++) {
                int k = k0 + wk + q;
                wbuf[q] = (k < K) ? wrow[k] : 0.f;
            }
        }
    };
    auto loadX = [&](int k0) {
        int k = k0 + xk;
        if constexpr (K % 16 != 0) {
            if (k >= K) {
#pragma unroll
                for (int q = 0; q < 8; q++) xbuf[q] = 0.f;
                return;
            }
        }
        int ci = k / 27, tap = k - ci * 27;
        int kt = tap / 9, r9 = tap - kt * 9;
        int kh = r9 / 3,  kw = r9 - kh * 3;
        int it  = t0 + kt - 1;
        int ih  = 2 * h0 + kh - 1;
        int iw0 = 2 * w0 + kw - 1;
        bool okp = ((unsigned)it < (unsigned)IT) && ((unsigned)ih < (unsigned)IH);
        const float* px = xb + ((size_t)ci * IT + it) * (IH * IW) + (long)ih * IW;
#pragma unroll
        for (int q = 0; q < 8; q++) {
            int iw = iw0 + 2 * q;
            bool ok = okp && ((unsigned)iw < (unsigned)IW);
            xbuf[q] = ok ? px[iw] : 0.f;
        }
    };

    loadW(0);
    loadX(0);

    for (int c0 = 0; c0 < NCH; c0++) {
        __syncthreads();
#pragma unroll
        for (int q = 0; q < 8; q++) Ws[wk + q][wc] = wbuf[q];
        *(float4*)&Xs[xk][xp]     = *(float4*)&xbuf[0];
        *(float4*)&Xs[xk][xp + 4] = *(float4*)&xbuf[4];
        __syncthreads();
        if (c0 + 1 < NCH) { loadW((c0 + 1) * 16); loadX((c0 + 1) * 16); }

#pragma unroll
        for (int kk = 0; kk < 16; kk++) {
            float a[8], bxr[8];
            *(float4*)&a[0]   = *(const float4*)&Ws[kk][tr * 8];
            *(float4*)&a[4]   = *(const float4*)&Ws[kk][tr * 8 + 4];
            *(float4*)&bxr[0] = *(const float4*)&Xs[kk][tc * 8];
            *(float4*)&bxr[4] = *(const float4*)&Xs[kk][tc * 8 + 4];
#pragma unroll
            for (int i = 0; i < 8; i++)
#pragma unroll
                for (int j = 0; j < 8; j++)
                    acc[i][j] = fmaf(a[i], bxr[j], acc[i][j]);
        }
    }

#pragma unroll
    for (int i = 0; i < 8; i++) {
        int co = cot + tr * 8 + i;
        float bv = bias[co];
        float o[8];
#pragma unroll
        for (int j = 0; j < 8; j++) {
            float v = acc[i][j] + bv;
            if (RELU) v = fmaxf(v, 0.f);
            o[j] = v;
        }
        float* yp = y + (size_t)(b * CO + co) * SPO + sp0 + tc * 8;
        *(float4*)yp       = *(float4*)&o[0];
        *(float4*)(yp + 4) = *(float4*)&o[4];
        if constexpr (FSPLIT) {
            int kt = co >> 3, kc = co & 7;
            int lc = kc & 3, khalf = kc >> 2;
#pragma unroll
            for (int j = 0; j < 8; j++) {
                int pos = pt + tc * 8 + j;
                int r   = pos & 15;
                int lane = (r & 7) * 4 + lc;
                int q    = khalf * 2 + (r >> 3);
                af[((size_t)((pos >> 4) * 64 + kt) * 32 + lane) * 4 + q] = tf32of(o[j]);
            }
        }
    }
}

// conv2 (plain)
template<int CIN, int CO, int OT, int IH, int IW, int OH, int OW, bool RELU>
__global__ void __launch_bounds__(256, 2) conv3d_kernel(
    const float* __restrict__ x, const float* __restrict__ w,
    const float* __restrict__ bias, float* __restrict__ y)
{
    conv3d_body<CIN, CO, OT, IH, IW, OH, OW, RELU, false>(
        x, w, bias, y, nullptr, blockIdx.x, blockIdx.y);
}

// conv1 grid-fused with codebook fragment split + c2
__global__ void __launch_bounds__(256, 2) conv1_cb_kernel(
    const float* __restrict__ x, const float* __restrict__ w,
    const float* __restrict__ bias, float* __restrict__ y,
    const float* __restrict__ cb, float* __restrict__ bf, float* __restrict__ c2)
{
    if (blockIdx.x < 1024) {
        conv3d_body<3, 128, 16, 128, 128, 64, 64, true, false>(
            x, w, bias, y, nullptr, blockIdx.x, 0);
        return;
    }
    const int blk  = blockIdx.x - 1024;          // 0..255
    const int wid  = threadIdx.x >> 5;
    const int lane = threadIdx.x & 31;
    const int lr = lane >> 2, lc = lane & 3;
    const int nt = blk * 4 + (wid & 3);
    const float* row = cb + (size_t)(nt * 8 + lr) * 512;
    for (int i = 0; i < 32; i++) {
        int kt = (wid >> 2) + 2 * i;
        float b0 = tf32of(row[kt * 8 + lc]);
        float b1 = tf32of(row[kt * 8 + lc + 4]);
        *(float2*)(bf + ((size_t)(nt * 64 + kt) * 32 + lane) * 2) = make_float2(b0, b1);
    }
#pragma unroll
    for (int rr = 0; rr < 4; rr++) {
        int v = blk * 32 + wid * 4 + rr;
        const float* r = cb + (size_t)v * 512;
        float s = 0.f;
#pragma unroll 4
        for (int c = lane; c < 512; c += 32) { float xv = r[c]; s = fmaf(xv, xv, s); }
#pragma unroll
        for (int off = 16; off; off >>= 1) s += __shfl_down_sync(0xffffffffu, s, off);
        if (lane == 0) c2[v] = s;
    }
}

// conv3 with A-fragment scatter fused in epilogue
__global__ void __launch_bounds__(256, 2) conv3_fs_kernel(
    const float* __restrict__ x, const float* __restrict__ w,
    const float* __restrict__ bias, float* __restrict__ y, float* __restrict__ af)
{
    conv3d_body<256, 512, 16, 32, 32, 16, 16, false, true>(
        x, w, bias, y, af, blockIdx.x, blockIdx.y);
}

// ---------------------------------------------------------------------------
// Pass 1: single-MMA tf32 approx distances, best-2 per (pos, segment).
// grid (64 pos-tiles, 8 segments), 256 threads, 2 CTAs/SM.
// 32-k chunks (16 per tile), 3-stage cp.async pipeline, 1 sync per chunk.
// Stage (8192 floats): A [mtl(8)][ktl(4)][128], B at +4096 [ntl(16)][ktl(4)][64]
// (R13 version — measured 431us, tensor 52.9%)
// ---------------------------------------------------------------------------
static constexpr int P1_SMEM = 3 * 8192 * 4;   // 96 KB

__global__ void __launch_bounds__(256, 2) vq_p1_kernel(
    const float* __restrict__ Af, const float* __restrict__ Bf,
    const float* __restrict__ c2,
    float* __restrict__ partS, int* __restrict__ partI)
{
    extern __shared__ float sm[];

    const int tid  = threadIdx.x;
    const int lane = tid & 31;
    const int wid  = tid >> 5;
    const int lr   = lane >> 2, lc = lane & 3;
    const int mw   = wid >> 2,  nw = wid & 3;

    const int pt  = blockIdx.x * 128;
    const int seg = blockIdx.y;
    const int mt0 = blockIdx.x * 8;

    // per-thread loader slots (4 A + 4 B), pointer-based addressing
    const float* aBase[4];
    uint32_t     aDst[4];
    size_t       bOffSrc[4];
    uint32_t     bDst[4];
#pragma unroll
    for (int i = 0; i < 4; i++) {
        int slot = tid + i * 256;                 // 0..1023
        int ln  = slot & 31;
        int ktA = (slot >> 5) & 3;
        int mtl = slot >> 7;                      // 0..7
        aBase[i] = Af + ((size_t)((mt0 + mtl) * 64 + ktA) * 32 + ln) * 4;
        aDst[i]  = (uint32_t)((mtl * 4 + ktA) * 128 + ln * 4);
        int lp  = slot & 15;
        int ktB = (slot >> 4) & 3;
        int ntl = slot >> 6;                      // 0..15
        bOffSrc[i] = ((size_t)(ntl * 64 + ktB) * 32 + lp * 2) * 2;
        bDst[i]    = (uint32_t)(4096 + (ntl * 4 + ktB) * 64 + lp * 4);
    }

    float s1[8], s2[8];
    int   i1[8], i2[8];
#pragma unroll
    for (int i = 0; i < 8; i++) { s1[i] = 3.4e38f; s2[i] = 3.4e38f; i1[i] = 0; i2[i] = 0; }

    for (int tile = 0; tile < 8; tile++) {
        const int nt0 = seg * 128 + tile * 16;
        const int vt  = seg * 1024 + tile * 128;
        const float* bTile = Bf + (size_t)nt0 * 4096;

        float acc[4][4][4];
#pragma unroll
        for (int a = 0; a < 4; a++)
#pragma unroll
            for (int c = 0; c < 4; c++)
#pragma unroll
                for (int r = 0; r < 4; r++) acc[a][c][r] = 0.f;

        auto issue = [&](int ch, int s) {
            uint32_t st = smem_u32(sm + s * 8192);
#pragma unroll
            for (int i = 0; i < 4; i++)
                cp16(st + aDst[i] * 4, aBase[i] + ch * 512);
#pragma unroll
            for (int i = 0; i < 4; i++)
                cp16(st + bDst[i] * 4, bTile + bOffSrc[i] + ch * 256);
            cpcommit();
        };

        issue(0, 0);
        issue(1, 1);
        for (int ch = 0; ch < 16; ch++) {
            if (ch < 15) cpwait<1>(); else cpwait<0>();
            __syncthreads();
            if (ch + 2 < 16) issue(ch + 2, (ch + 2) % 3);

            const float* st = sm + (ch % 3) * 8192;
#pragma unroll
            for (int ktl = 0; ktl < 4; ktl++) {
                uint32_t ah[4][4], bh[4][2];
#pragma unroll
                for (int mf = 0; mf < 4; mf++)
                    *(float4*)&ah[mf][0] = *(const float4*)(
                        st + ((mw * 4 + mf) * 4 + ktl) * 128 + lane * 4);
#pragma unroll
                for (int nf = 0; nf < 4; nf++)
                    *(float2*)&bh[nf][0] = *(const float2*)(
                        st + 4096 + ((nw * 4 + nf) * 4 + ktl) * 64 + lane * 2);
#pragma unroll
                for (int mf = 0; mf < 4; mf++)
#pragma unroll
                    for (int nf = 0; nf < 4; nf++)
                        mma8(acc[mf][nf], ah[mf], bh[nf]);
            }
        }
        __syncthreads();   // stage reuse across tiles

#pragma unroll
        for (int mf = 0; mf < 4; mf++)
#pragma unroll
            for (int half = 0; half < 2; half++) {
                int bs = mf * 2 + half;
#pragma unroll
                for (int nf = 0; nf < 4; nf++)
#pragma unroll
                    for (int r = 0; r < 2; r++) {
                        int col = vt + (nw * 4 + nf) * 8 + 2 * lc + r;
                        float d = fmaf(-2.f, acc[mf][nf][half * 2 + r],
                                       __ldg(&c2[col]));
                        if (d < s1[bs]) {
                            s2[bs] = s1[bs]; i2[bs] = i1[bs];
                            s1[bs] = d;      i1[bs] = col;
                        } else if (d < s2[bs]) {
                            s2[bs] = d;      i2[bs] = col;
                        }
                    }
            }
    }

    // reduction: 16 contributors x best-2 per row
    __syncthreads();
    float* redS = sm;                 // [128][32]
    int*   redI = (int*)(sm + 4096);  // [128][32]
#pragma unroll
    for (int mf = 0; mf < 4; mf++)
#pragma unroll
        for (int half = 0; half < 2; half++) {
            int bs   = mf * 2 + half;
            int row  = mw * 64 + mf * 16 + half * 8 + lr;
            int cont = nw * 4 + lc;
            redS[row * 32 + cont * 2]     = s1[bs];
            redS[row * 32 + cont * 2 + 1] = s2[bs];
            redI[row * 32 + cont * 2]     = i1[bs];
            redI[row * 32 + cont * 2 + 1] = i2[bs];
        }
    __syncthreads();
    if (tid < 128) {
        float b1 = 3.4e38f, b2 = 3.4e38f;
        int   j1 = 0, j2 = 0;
#pragma unroll
        for (int q = 0; q < 32; q++) {
            float v = redS[tid * 32 + q];
            int   i = redI[tid * 32 + q];
            if (v < b1) { b2 = b1; j2 = j1; b1 = v; j1 = i; }
            else if (v < b2) { b2 = v; j2 = i; }
        }
        int pos = pt + tid;
        partS[(seg * 2 + 0) * 8192 + pos] = b1;
        partI[(seg * 2 + 0) * 8192 + pos] = j1;
        partS[(seg * 2 + 1) * 8192 + pos] = b2;
        partI[(seg * 2 + 1) * 8192 + pos] = j2;
    }
}

// ---------------------------------------------------------------------------
// Pass 2: exact fp32 re-score of 16 candidates per position; the winning
// warp then copies the embedding row (gather fused). One warp/pos.
// ---------------------------------------------------------------------------
__global__ void __launch_bounds__(256) vq_p2_kernel(
    const float* __restrict__ f, const float* __restrict__ cb,
    const int* __restrict__ partI, const float* __restrict__ emb,
    float* __restrict__ outTok, float* __restrict__ outEmb, int writeTok)
{
    const int wid  = threadIdx.x >> 5;
    const int lane = threadIdx.x & 31;
    const int pos  = blockIdx.x * 8 + wid;
    const int b    = pos >> 12;
    const int sp   = pos & 4095;

    float fv[16];
#pragma unroll
    for (int t = 0; t < 16; t++)
        fv[t] = f[((size_t)b * 512 + lane + 32 * t) * 4096 + sp];

    float best = 3.4e38f;
    int   bi   = 0x7fffffff;
#pragma unroll 1
    for (int j = 0; j < 16; j++) {
        int v = partI[j * 8192 + pos];
        const float* cr = cb + (size_t)v * 512;
        float dot = 0.f, cc = 0.f;
#pragma unroll
        for (int t = 0; t < 16; t++) {
            float cv = cr[lane + 32 * t];
            dot = fmaf(fv[t], cv, dot);
            cc  = fmaf(cv, cv, cc);
        }
#pragma unroll
        for (int off = 16; off; off >>= 1) {
            dot += __shfl_down_sync(0xffffffffu, dot, off);
            cc  += __shfl_down_sync(0xffffffffu, cc,  off);
        }
        if (lane == 0) {
            float d = fmaf(-2.f, dot, cc);
            if (d < best || (d == best && v < bi)) { best = d; bi = v; }
        }
    }
    bi = __shfl_sync(0xffffffffu, bi, 0);
    if (lane == 0 && writeTok) outTok[pos] = (float)bi;
    const float4* src = (const float4*)(emb + (size_t)bi * 512);
    float4*       dst = (float4*)(outEmb + (size_t)pos * 512);
#pragma unroll
    for (int t = 0; t < 4; t++)
        dst[lane + 32 * t] = src[lane + 32 * t];
}

// ---------------------------------------------------------------------------
// launch (vq_p1 is the 4th launch -> profiled by ncu)
// ---------------------------------------------------------------------------
extern "C" void kernel_launch(void* const* d_in, const int* in_sizes, int n_in,
                              void* d_out, int out_size)
{
    const float* video = (const float*)d_in[0];
    const float* w1    = (const float*)d_in[1];
    const float* b1    = (const float*)d_in[2];
    const float* w2    = (const float*)d_in[3];
    const float* b2    = (const float*)d_in[4];
    const float* w3    = (const float*)d_in[5];
    const float* b3    = (const float*)d_in[6];
    const float* cb    = (const float*)d_in[7];
    const float* emb   = (const float*)d_in[8];

    float *h1, *h2, *ff, *af, *bf, *c2, *ps;
    int *pi;
    cudaGetSymbolAddress((void**)&h1, g_h1);
    cudaGetSymbolAddress((void**)&h2, g_h2);
    cudaGetSymbolAddress((void**)&ff, g_f);
    cudaGetSymbolAddress((void**)&af, g_Af);
    cudaGetSymbolAddress((void**)&bf, g_Bf);
    cudaGetSymbolAddress((void**)&c2, g_c2);
    cudaGetSymbolAddress((void**)&ps, g_ps);
    cudaGetSymbolAddress((void**)&pi, g_pi);

    cudaFuncSetAttribute(vq_p1_kernel,
                         cudaFuncAttributeMaxDynamicSharedMemorySize, P1_SMEM);

    // 1: conv1 + codebook fragment split + c2
    conv1_cb_kernel<<<1024 + 256, 256>>>(video, w1, b1, h1, cb, bf, c2);
    // 2: conv2
    conv3d_kernel<128, 256, 16, 64, 64, 32, 32, true>
        <<<dim3(256, 2), 256>>>(h1, w2, b2, h2);
    // 3: conv3 + f fragment scatter
    conv3_fs_kernel<<<dim3(64, 4), 256>>>(h2, w3, b3, ff, af);
    // 4: VQ pass 1 (profiled)
    vq_p1_kernel<<<dim3(64, 8), 256, P1_SMEM>>>(af, bf, c2, ps, pi);

    float* outf = (float*)d_out;
    const int embElems = 8192 * 512;
    int writeTok = (out_size >= embElems + 8192) ? 1 : 0;
    float* embOut = outf + (writeTok ? 8192 : 0);

    // 5: VQ pass 2 (exact re-score + fused embedding gather)
    vq_p2_kernel<<<1024, 256>>>(ff, cb, pi, emb, outf, embOut, writeTok);
}